// round 7
// baseline (speedup 1.0000x reference)
#include <cuda_runtime.h>

// h_t = alpha_t * h_{t-1} + x_t over axis 1 of float32 [4, 8192, 1024].
// Persistent: one block per (batch, 32-d tile) chain = 128 blocks, each block
// scans S=8192 in 32 chunks of 256 steps, register double-buffered prefetch.
// R7: float4 memory path (LDG.128/STG.128) to lift the per-SM LSU-issue floor;
// warp = 8 d-quads x 4 row-groups, shuffle-scan combines row-groups in-warp.

#define B_      4
#define S_      8192
#define D_      1024
#define TPB_    512
#define DTILE_  32                    // d-lanes per block
#define RQ_     4                     // contiguous s-rows per thread
#define ROWSW_  16                    // s-rows per warp (4 groups x RQ_)
#define SUBS_   16                    // warps per block
#define CHUNK_  (SUBS_ * ROWSW_)      // 256 s-steps per chunk
#define ITERS_  (S_ / CHUNK_)         // 32 chunks
#define LG_     (B_ * (D_ / DTILE_))  // 128 chains = 128 blocks

static __device__ __forceinline__ float4 fma4(float4 a, float4 b, float4 c) {
    float4 r;
    r.x = fmaf(a.x, b.x, c.x); r.y = fmaf(a.y, b.y, c.y);
    r.z = fmaf(a.z, b.z, c.z); r.w = fmaf(a.w, b.w, c.w);
    return r;
}
static __device__ __forceinline__ float4 mul4(float4 a, float4 b) {
    return make_float4(a.x * b.x, a.y * b.y, a.z * b.z, a.w * b.w);
}
static __device__ __forceinline__ float4 shfl_up4(float4 v, int delta) {
    float4 r;
    r.x = __shfl_up_sync(0xffffffffu, v.x, delta);
    r.y = __shfl_up_sync(0xffffffffu, v.y, delta);
    r.z = __shfl_up_sync(0xffffffffu, v.z, delta);
    r.w = __shfl_up_sync(0xffffffffu, v.w, delta);
    return r;
}
static __device__ __forceinline__ float4 shfl_idx4(float4 v, int src) {
    float4 r;
    r.x = __shfl_sync(0xffffffffu, v.x, src);
    r.y = __shfl_sync(0xffffffffu, v.y, src);
    r.z = __shfl_sync(0xffffffffu, v.z, src);
    r.w = __shfl_sync(0xffffffffu, v.w, src);
    return r;
}

// One chunk. CUR/NXT: register ping-pong buffers. Order: local scan ->
// warp shuffle-scan -> STS -> prefetch(K+1) -> barrier -> block fold ->
// stores. Prefetch LDGs are issued before the barrier so DRAM streams
// through the sync/fold section.
#define BODY(CUR, NXT, K)                                                     \
    {                                                                         \
        /* local scan over RQ_ contiguous rows (per d-quad) */                \
        float4 P = make_float4(1.f, 1.f, 1.f, 1.f);                           \
        float4 L = make_float4(0.f, 0.f, 0.f, 0.f);                           \
        _Pragma("unroll")                                                     \
        for (int r = 0; r < RQ_; r++) {                                       \
            L = fma4(A[CUR][r], L, X[CUR][r]);                                \
            P = mul4(P, A[CUR][r]);                                           \
            A[CUR][r] = P;   /* cumprod through row r   */                    \
            X[CUR][r] = L;   /* local scan through row r */                   \
        }                                                                     \
        /* warp-level inclusive scan across the 4 row-groups */               \
        float4 Pi = P, Li = L;                                                \
        {                                                                     \
            float4 pp = shfl_up4(Pi, 8), lp = shfl_up4(Li, 8);                \
            if (lane >= 8)  { Li = fma4(Pi, lp, Li); Pi = mul4(Pi, pp); }     \
        }                                                                     \
        {                                                                     \
            float4 pp = shfl_up4(Pi, 16), lp = shfl_up4(Li, 16);              \
            if (lane >= 16) { Li = fma4(Pi, lp, Li); Pi = mul4(Pi, pp); }     \
        }                                                                     \
        /* exclusive prefix transform for this thread's group */              \
        float4 Pe = shfl_up4(Pi, 8), Le = shfl_up4(Li, 8);                    \
        if (lane < 8) { Pe = make_float4(1.f,1.f,1.f,1.f);                    \
                        Le = make_float4(0.f,0.f,0.f,0.f); }                  \
        /* warp aggregate = inclusive at last group (lanes 24-31) */          \
        float4 Pw = shfl_idx4(Pi, 24 + dq);                                   \
        float4 Lw = shfl_idx4(Li, 24 + dq);                                   \
        if (lane < 8) { sp[CUR][w][dq] = Pw; sl[CUR][w][dq] = Lw; }           \
        /* prefetch chunk K+1 (before the barrier) */                         \
        const size_t nbase = base + (size_t)CHUNK_ * D_;                      \
        if ((K) + 1 < ITERS_) {                                               \
            _Pragma("unroll")                                                 \
            for (int r = 0; r < RQ_; r++)                                     \
                A[NXT][r] = __ldcs((const float4*)(alpha + nbase + (size_t)r * D_)); \
            _Pragma("unroll")                                                 \
            for (int r = 0; r < RQ_; r++)                                     \
                X[NXT][r] = __ldcs((const float4*)(x + nbase + (size_t)r * D_)); \
        }                                                                     \
        __syncthreads();                                                      \
        /* block fold over 16 warp aggregates (per d-quad) */                 \
        float4 acc = cin, hw = cin;                                           \
        _Pragma("unroll")                                                     \
        for (int w2 = 0; w2 < SUBS_; w2++) {                                  \
            if (w2 == w) hw = acc;                                            \
            acc = fma4(sp[CUR][w2][dq], acc, sl[CUR][w2][dq]);                \
        }                                                                     \
        cin = acc;                                                            \
        /* carry at this thread's first row, then store */                    \
        float4 h0 = fma4(Pe, hw, Le);                                         \
        _Pragma("unroll")                                                     \
        for (int r = 0; r < RQ_; r++) {                                       \
            float4 o = fma4(A[CUR][r], h0, X[CUR][r]);                        \
            __stcs((float4*)(out + base + (size_t)r * D_), o);                \
        }                                                                     \
        base = nbase;                                                         \
    }

__global__ __launch_bounds__(TPB_, 1) void scan_kernel(const float* __restrict__ x,
                                                       const float* __restrict__ alpha,
                                                       float* __restrict__ out) {
    // Double-buffered warp aggregates: one sync per chunk is race-free
    // (sync at k+1 separates read(k) from write(k+2) of the same buffer).
    __shared__ float4 sp[2][SUBS_][8];
    __shared__ float4 sl[2][SUBS_][8];

    const int tid  = threadIdx.x;
    const int lane = tid & 31;
    const int w    = tid >> 5;           // warp = 16-row slab within chunk
    const int dq   = lane & 7;           // d-quad within the 32-d tile
    const int g    = lane >> 3;          // row-group within warp (0..3)
    const int lg   = blockIdx.x;         // chain: b * 32 + dtile
    const int b    = lg >> 5;
    const int dt   = lg & 31;
    const int d    = dt * DTILE_ + dq * 4;
    const int row0 = w * ROWSW_ + g * RQ_;   // first row within chunk

    size_t base = ((size_t)b * S_ + row0) * (size_t)D_ + d;

    float4 A[2][RQ_], X[2][RQ_];
    float4 cin = make_float4(0.f, 0.f, 0.f, 0.f);

    // Preload chunk 0.
#pragma unroll
    for (int r = 0; r < RQ_; r++)
        A[0][r] = __ldcs((const float4*)(alpha + base + (size_t)r * D_));
#pragma unroll
    for (int r = 0; r < RQ_; r++)
        X[0][r] = __ldcs((const float4*)(x + base + (size_t)r * D_));

#pragma unroll 1
    for (int k = 0; k < ITERS_; k += 2) {
        BODY(0, 1, k)
        BODY(1, 0, k + 1)
    }
}

extern "C" void kernel_launch(void* const* d_in, const int* in_sizes, int n_in,
                              void* d_out, int out_size) {
    const float* xp = (const float*)d_in[0];
    const float* ap = (const float*)d_in[1];
    float* op = (float*)d_out;

    scan_kernel<<<LG_, TPB_>>>(xp, ap, op);
}

// round 8
// speedup vs baseline: 1.1339x; 1.1339x over previous
#include <cuda_runtime.h>

// h_t = alpha_t * h_{t-1} + x_t over axis 1 of float32 [4, 8192, 1024].
// Persistent scan, R6 skeleton with halved chain width for 2 co-resident
// blocks/SM: one block's streaming hides the other's barrier/fold bubble.
// One block per (batch, 16-wide d-tile) chain = 256 blocks. Each block scans
// S=8192 in 32 chunks of 256 rows with register double-buffered prefetch.
// No flags, no atomics, no fences, one __syncthreads per chunk.

#define B_      4
#define S_      8192
#define D_      1024
#define R_      16                    // s-rows per thread per chunk
#define TPB_    256                   // 8 warps
#define DTILE_  16                    // d-lanes per block
#define NSUB_   16                    // s-subchunks per chunk (8 warps x 2 groups)
#define CHUNK_  (NSUB_ * R_)          // 256 s-rows per chunk
#define ITERS_  (S_ / CHUNK_)         // 32 chunks per chain
#define LG_     (B_ * (D_ / DTILE_))  // 256 chains = 256 blocks

// One chunk body. CUR/NXT: register ping-pong. Prefetch LDGs for chunk K+1
// issue BEFORE the barrier/fold/stores of chunk K so DRAM streams through
// the serial section.
#define BODY(CUR, NXT, K)                                                     \
    {                                                                         \
        const size_t nbase = base + (size_t)CHUNK_ * D_;                      \
        if ((K) + 1 < ITERS_) {                                               \
            _Pragma("unroll")                                                 \
            for (int r = 0; r < R_; r++)                                      \
                A[NXT][r] = __ldcs(alpha + nbase + (size_t)r * D_);           \
            _Pragma("unroll")                                                 \
            for (int r = 0; r < R_; r++)                                      \
                X[NXT][r] = __ldcs(x + nbase + (size_t)r * D_);               \
        }                                                                     \
        float P = 1.0f, L = 0.0f;                                             \
        _Pragma("unroll")                                                     \
        for (int r = 0; r < R_; r++) {                                        \
            L = fmaf(A[CUR][r], L, X[CUR][r]);                                \
            P = P * A[CUR][r];                                                \
            A[CUR][r] = P;   /* per-step cumprod     */                       \
            X[CUR][r] = L;   /* per-step local scan  */                       \
        }                                                                     \
        sp[CUR][sub][dlane] = P;                                              \
        sl[CUR][sub][dlane] = L;                                              \
        __syncthreads();                                                      \
        /* every thread folds the 16 sub-aggregates for its d-lane:        */\
        /* h0 = prefix before own sub, acc = full fold -> next carry.      */\
        float acc = cin, h0 = cin;                                            \
        _Pragma("unroll")                                                     \
        for (int w2 = 0; w2 < NSUB_; w2++) {                                  \
            if (w2 == sub) h0 = acc;                                          \
            acc = fmaf(sp[CUR][w2][dlane], acc, sl[CUR][w2][dlane]);          \
        }                                                                     \
        cin = acc;                                                            \
        _Pragma("unroll")                                                     \
        for (int r = 0; r < R_; r++)                                          \
            __stcs(out + base + (size_t)r * D_, fmaf(A[CUR][r], h0, X[CUR][r]));\
        base = nbase;                                                         \
    }

__global__ __launch_bounds__(TPB_, 2) void scan_kernel(const float* __restrict__ x,
                                                       const float* __restrict__ alpha,
                                                       float* __restrict__ out) {
    // Double-buffered sub-aggregates: one sync per chunk is race-free
    // (sync at k+1 separates read(k) from write(k+2) of the same buffer).
    __shared__ float sp[2][NSUB_][DTILE_];
    __shared__ float sl[2][NSUB_][DTILE_];

    const int tid   = threadIdx.x;
    const int lane  = tid & 31;
    const int w     = tid >> 5;          // warp 0..7
    const int dlane = lane & 15;         // d within tile
    const int rg    = lane >> 4;         // row-group within warp (0..1)
    const int sub   = w * 2 + rg;        // s-subchunk index (0..15)
    const int lg    = blockIdx.x;        // chain: b * 64 + dtile
    const int b     = lg >> 6;
    const int dt    = lg & 63;
    const int d     = dt * DTILE_ + dlane;

    size_t base = ((size_t)b * S_ + (size_t)sub * R_) * (size_t)D_ + d;

    float A[2][R_], X[2][R_];
    float cin = 0.0f;

    // Preload chunk 0.
#pragma unroll
    for (int r = 0; r < R_; r++) A[0][r] = __ldcs(alpha + base + (size_t)r * D_);
#pragma unroll
    for (int r = 0; r < R_; r++) X[0][r] = __ldcs(x + base + (size_t)r * D_);

#pragma unroll 1
    for (int k = 0; k < ITERS_; k += 2) {
        BODY(0, 1, k)
        BODY(1, 0, k + 1)
    }
}

extern "C" void kernel_launch(void* const* d_in, const int* in_sizes, int n_in,
                              void* d_out, int out_size) {
    const float* xp = (const float*)d_in[0];
    const float* ap = (const float*)d_in[1];
    float* op = (float*)d_out;

    scan_kernel<<<LG_, TPB_>>>(xp, ap, op);
}